// round 1
// baseline (speedup 1.0000x reference)
#include <cuda_runtime.h>
#include <cuda_bf16.h>
#include <math.h>

#define N_NODES 65536
#define N_EDGES 524288
#define HIDDEN 128
#define OUTDIM 10
#define NUM_GRAPHS 64
#define SLOT_CAP 64

// ---------------- scratch (device globals; no allocation allowed) ----------
__device__ __align__(16) static float g_agg[(size_t)N_NODES * HIDDEN];
__device__ __align__(16) static float g_h[(size_t)N_NODES * HIDDEN];
__device__ static int   g_deg[N_NODES];
__device__ static int   g_slots[(size_t)N_NODES * SLOT_CAP];
__device__ static float g_gsum[NUM_GRAPHS * HIDDEN];
__device__ static float g_gcnt[NUM_GRAPHS];
__device__ static int   g_is64;

// ---------------- index dtype detection ------------------------------------
// Values are node/graph ids < 65536. If stored as little-endian int64, every
// odd 32-bit word is zero. If int32, the odd words are random ids (P[all
// zero] ~ (1/65536)^128 = 0). Deterministic for fixed inputs.
__global__ void detect_kernel(const unsigned int* __restrict__ w) {
    bool is64 = true;
    for (int i = 1; i < 256; i += 2) {
        if (w[i] != 0u) { is64 = false; break; }
    }
    g_is64 = is64 ? 1 : 0;
}

__device__ __forceinline__ int load_idx(const void* p, int i, int is64) {
    if (is64) return (int)((const long long*)p)[i];
    return ((const int*)p)[i];
}

// ---------------- zero scratch ----------------------------------------------
__global__ void zero_kernel() {
    int i = blockIdx.x * blockDim.x + threadIdx.x;
    if (i < N_NODES) g_deg[i] = 0;
    if (i < NUM_GRAPHS * HIDDEN) g_gsum[i] = 0.0f;
    if (i < NUM_GRAPHS) g_gcnt[i] = 0.0f;
}

// ---------------- bucketed inverse adjacency (built once per launch) --------
__global__ void build_kernel(const void* __restrict__ src,
                             const void* __restrict__ dst) {
    int e = blockIdx.x * blockDim.x + threadIdx.x;
    if (e >= N_EDGES) return;
    int is64 = g_is64;
    int d = load_idx(dst, e, is64);
    int s = load_idx(src, e, is64);
    int pos = atomicAdd(&g_deg[d], 1);
    if (pos < SLOT_CAP) g_slots[(size_t)d * SLOT_CAP + pos] = s;
}

// ---------------- per-node gather-sum (no float atomics) ---------------------
// One warp per node; lane owns 4 contiguous columns (float4). Slot indices are
// preloaded into 2 regs and broadcast via shfl so the inner loop's loads are
// independent (good MLP).
__global__ void gather_kernel(const float* __restrict__ hin,
                              float* __restrict__ agg) {
    int w = (blockIdx.x * blockDim.x + threadIdx.x) >> 5;
    int lane = threadIdx.x & 31;
    if (w >= N_NODES) return;
    int deg = g_deg[w];
    if (deg > SLOT_CAP) deg = SLOT_CAP;
    const int* slots = g_slots + (size_t)w * SLOT_CAP;
    int s0 = (lane < deg) ? slots[lane] : 0;
    int s1 = (32 + lane < deg) ? slots[32 + lane] : 0;
    float4 acc = make_float4(0.f, 0.f, 0.f, 0.f);
    for (int i = 0; i < deg; i++) {
        int s = __shfl_sync(0xffffffffu, (i < 32) ? s0 : s1, i & 31);
        float4 v = __ldg((const float4*)(hin + (size_t)s * HIDDEN) + lane);
        acc.x += v.x; acc.y += v.y; acc.z += v.z; acc.w += v.w;
    }
    ((float4*)(agg + (size_t)w * HIDDEN))[lane] = acc;
}

// ---------------- fused GEMM (A[rows,128] @ W[128,128] + b) -> ELU -----------
// Block = 256 threads = 8 warps, 32 rows per block, 128 cols.
// Warp handles 4 rows; lane handles 4 cols -> 4x4 register tile.
// Dynamic smem: W (64KB) + A tile (16KB) = 80KB.
__global__ void gemm_elu_kernel(const float* __restrict__ A,
                                const float* __restrict__ W,
                                const float* __restrict__ b,
                                float* __restrict__ out) {
    extern __shared__ float smem[];
    float* Ws = smem;             // 128*128
    float* As = smem + 128 * 128; // 32*128
    int tid = threadIdx.x;

    const float4* W4 = (const float4*)W;
    float4* Ws4 = (float4*)Ws;
#pragma unroll
    for (int i = tid; i < 128 * 32; i += 256) Ws4[i] = W4[i];

    int rowBase = blockIdx.x * 32;
    const float4* A4 = (const float4*)(A + (size_t)rowBase * HIDDEN);
    float4* As4 = (float4*)As;
#pragma unroll
    for (int i = tid; i < 32 * 32; i += 256) As4[i] = A4[i];
    __syncthreads();

    int warp = tid >> 5, lane = tid & 31;
    int r0 = warp * 4;

    float4 bb = ((const float4*)b)[lane];
    float acc[4][4];
#pragma unroll
    for (int r = 0; r < 4; r++) {
        acc[r][0] = bb.x; acc[r][1] = bb.y; acc[r][2] = bb.z; acc[r][3] = bb.w;
    }

#pragma unroll 8
    for (int k = 0; k < 128; k++) {
        float4 w = Ws4[k * 32 + lane];
        float a0 = As[(r0 + 0) * 128 + k];
        float a1 = As[(r0 + 1) * 128 + k];
        float a2 = As[(r0 + 2) * 128 + k];
        float a3 = As[(r0 + 3) * 128 + k];
        acc[0][0] += a0 * w.x; acc[0][1] += a0 * w.y; acc[0][2] += a0 * w.z; acc[0][3] += a0 * w.w;
        acc[1][0] += a1 * w.x; acc[1][1] += a1 * w.y; acc[1][2] += a1 * w.z; acc[1][3] += a1 * w.w;
        acc[2][0] += a2 * w.x; acc[2][1] += a2 * w.y; acc[2][2] += a2 * w.z; acc[2][3] += a2 * w.w;
        acc[3][0] += a3 * w.x; acc[3][1] += a3 * w.y; acc[3][2] += a3 * w.z; acc[3][3] += a3 * w.w;
    }

#pragma unroll
    for (int r = 0; r < 4; r++) {
        float4 v;
        v.x = acc[r][0] > 0.f ? acc[r][0] : expm1f(acc[r][0]);
        v.y = acc[r][1] > 0.f ? acc[r][1] : expm1f(acc[r][1]);
        v.z = acc[r][2] > 0.f ? acc[r][2] : expm1f(acc[r][2]);
        v.w = acc[r][3] > 0.f ? acc[r][3] : expm1f(acc[r][3]);
        ((float4*)(out + (size_t)(rowBase + r0 + r) * HIDDEN))[lane] = v;
    }
}

// ---------------- graph readout ----------------------------------------------
__global__ void count_kernel(const void* __restrict__ gid) {
    int i = blockIdx.x * blockDim.x + threadIdx.x;
    if (i >= N_NODES) return;
    int g = load_idx(gid, i, g_is64);
    atomicAdd(&g_gcnt[g], 1.0f);
}

// graph_ids are sorted: accumulate runs in registers, flush on segment change.
// Block = 128 threads (one per column), 128 nodes per block.
__global__ void readout_kernel(const float* __restrict__ h,
                               const void* __restrict__ gid) {
    int t = threadIdx.x;
    int base = blockIdx.x * 128;
    int is64 = g_is64;
    int cur = load_idx(gid, base, is64);
    float acc = 0.0f;
    for (int n = 0; n < 128; n++) {
        int node = base + n;
        int g = load_idx(gid, node, is64);
        if (g != cur) {
            atomicAdd(&g_gsum[cur * HIDDEN + t], acc);
            acc = 0.0f; cur = g;
        }
        acc += h[(size_t)node * HIDDEN + t];
    }
    atomicAdd(&g_gsum[cur * HIDDEN + t], acc);
}

__global__ void classifier_kernel(const float* __restrict__ Wc,
                                  const float* __restrict__ bc,
                                  float* __restrict__ out) {
    int t = blockIdx.x * blockDim.x + threadIdx.x;
    if (t >= NUM_GRAPHS * OUTDIM) return;
    int g = t / OUTDIM, o = t % OUTDIM;
    float c = fmaxf(g_gcnt[g], 1.0f);
    float inv = 1.0f / c;
    float acc = bc[o];
#pragma unroll 8
    for (int k = 0; k < HIDDEN; k++)
        acc += g_gsum[g * HIDDEN + k] * inv * Wc[k * OUTDIM + o];
    out[t] = acc;
}

// ---------------- launch -------------------------------------------------------
extern "C" void kernel_launch(void* const* d_in, const int* in_sizes, int n_in,
                              void* d_out, int out_size) {
    const float* features = (const float*)d_in[0];
    const void*  src      = d_in[1];
    const void*  dst      = d_in[2];
    const void*  gids     = d_in[3];
    const float* W1 = (const float*)d_in[4];
    const float* b1 = (const float*)d_in[5];
    const float* W2 = (const float*)d_in[6];
    const float* b2 = (const float*)d_in[7];
    const float* W3 = (const float*)d_in[8];
    const float* b3 = (const float*)d_in[9];
    const float* Wc = (const float*)d_in[10];
    const float* bc = (const float*)d_in[11];
    float* out = (float*)d_out;

    float* agg; cudaGetSymbolAddress((void**)&agg, g_agg);
    float* h;   cudaGetSymbolAddress((void**)&h, g_h);

    const int GEMM_SMEM = (128 * 128 + 32 * 128) * (int)sizeof(float); // 80KB
    cudaFuncSetAttribute(gemm_elu_kernel,
                         cudaFuncAttributeMaxDynamicSharedMemorySize, GEMM_SMEM);

    detect_kernel<<<1, 1>>>((const unsigned int*)src);
    zero_kernel<<<N_NODES / 256, 256>>>();
    build_kernel<<<N_EDGES / 256, 256>>>(src, dst);

    const int GATHER_BLOCKS = (N_NODES * 32) / 256;
    const int GEMM_BLOCKS = N_NODES / 32;

    // layer 1
    gather_kernel<<<GATHER_BLOCKS, 256>>>(features, agg);
    gemm_elu_kernel<<<GEMM_BLOCKS, 256, GEMM_SMEM>>>(agg, W1, b1, h);
    // layer 2
    gather_kernel<<<GATHER_BLOCKS, 256>>>(h, agg);
    gemm_elu_kernel<<<GEMM_BLOCKS, 256, GEMM_SMEM>>>(agg, W2, b2, h);
    // layer 3
    gather_kernel<<<GATHER_BLOCKS, 256>>>(h, agg);
    gemm_elu_kernel<<<GEMM_BLOCKS, 256, GEMM_SMEM>>>(agg, W3, b3, h);

    // readout + classify
    count_kernel<<<N_NODES / 256, 256>>>(gids);
    readout_kernel<<<N_NODES / 128, 128>>>(h, gids);
    classifier_kernel<<<1, NUM_GRAPHS * OUTDIM>>>(Wc, bc, out);
}